// round 7
// baseline (speedup 1.0000x reference)
#include <cuda_runtime.h>
#include <cuda_bf16.h>
#include <cuda_fp16.h>
#include <cstdint>

// Problem constants
#define BB 64
#define TT 512
#define BT (BB*TT)          // 32768
#define GIN 1024
#define HID 1024
#define H3  3072
#define NIN 512
#define KOUT 1536

// ----------------------------- scratch (device globals)
__device__ float g_inp[(size_t)BT * GIN];                  // tf32-rounded [emb|z]
__device__ float g_xproj[(size_t)BT * H3];
__device__ float g_hall[(size_t)BT * HID];                 // tf32-rounded h, [b][t][H]
__device__ __half g_hhi[(size_t)TT * BB * HID];            // [t][b][H] fp16 hi
__device__ __half g_hlo[(size_t)TT * BB * HID];            // fp16 lo
__device__ float g_wih[(size_t)H3 * GIN];                  // tf32-rounded W_ih
__device__ float g_wout[(size_t)NIN * KOUT];               // tf32-rounded W_out
__device__ unsigned g_flags[128 * 8];                      // flags (32B apart)

// ----------------------------- helpers
__device__ __forceinline__ float to_tf32(float x) {
    unsigned u;
    asm("cvt.rna.tf32.f32 %0, %1;" : "=r"(u) : "f"(x));
    return __uint_as_float(u);
}
__device__ __forceinline__ void mma_tf32(float acc[4], const unsigned a[4],
                                         unsigned b0, unsigned b1) {
    asm volatile(
        "mma.sync.aligned.m16n8k8.row.col.f32.tf32.tf32.f32 "
        "{%0,%1,%2,%3},{%4,%5,%6,%7},{%8,%9},{%0,%1,%2,%3};"
        : "+f"(acc[0]), "+f"(acc[1]), "+f"(acc[2]), "+f"(acc[3])
        : "r"(a[0]), "r"(a[1]), "r"(a[2]), "r"(a[3]), "r"(b0), "r"(b1));
}
__device__ __forceinline__ void mma_f16(float acc[4], const unsigned a[4],
                                        unsigned b0, unsigned b1) {
    asm volatile(
        "mma.sync.aligned.m16n8k16.row.col.f32.f16.f16.f32 "
        "{%0,%1,%2,%3},{%4,%5,%6,%7},{%8,%9},{%0,%1,%2,%3};"
        : "+f"(acc[0]), "+f"(acc[1]), "+f"(acc[2]), "+f"(acc[3])
        : "r"(a[0]), "r"(a[1]), "r"(a[2]), "r"(a[3]), "r"(b0), "r"(b1));
}
__device__ __forceinline__ void ldsm4(unsigned r[4], uint32_t addr) {
    asm volatile("ldmatrix.sync.aligned.m8n8.x4.shared.b16 {%0,%1,%2,%3}, [%4];"
                 : "=r"(r[0]), "=r"(r[1]), "=r"(r[2]), "=r"(r[3]) : "r"(addr));
}
__device__ __forceinline__ void ldsm2(unsigned r[2], uint32_t addr) {
    asm volatile("ldmatrix.sync.aligned.m8n8.x2.shared.b16 {%0,%1}, [%2];"
                 : "=r"(r[0]), "=r"(r[1]) : "r"(addr));
}
__device__ __forceinline__ uint32_t smem_u32(const void* p) {
    uint32_t a;
    asm("{ .reg .u64 t; cvta.to.shared.u64 t, %1; cvt.u32.u64 %0, t; }" : "=r"(a) : "l"(p));
    return a;
}
__device__ __forceinline__ void cpasync16(uint32_t dst, const void* src) {
    asm volatile("cp.async.cg.shared.global [%0], [%1], 16;" :: "r"(dst), "l"(src) : "memory");
}
__device__ __forceinline__ void cp_commit() {
    asm volatile("cp.async.commit_group;" ::: "memory");
}
__device__ __forceinline__ float sigmoidf(float v) { return 1.0f / (1.0f + expf(-v)); }
__device__ __forceinline__ uint32_t pk2h(__half a, __half b) {
    __half2 t(a, b);
    return *(uint32_t*)&t;
}

// ----------------------------- kernel: gather emb + concat z (tf32) ; reset flags
__global__ void build_inp_kernel(const int* __restrict__ x,
                                 const float* __restrict__ z,
                                 const float* __restrict__ emb) {
    size_t idx = (size_t)blockIdx.x * 256 + threadIdx.x;
    if (idx < 1024) g_flags[idx] = 0u;
    int m = (int)(idx >> 10);
    int k = (int)(idx & 1023);
    int b = m >> 9;
    float v;
    if (k < 512) v = emb[(size_t)x[m] * 512 + k];
    else         v = z[b * 512 + (k - 512)];
    g_inp[idx] = to_tf32(v);
}

// ----------------------------- kernel: pre-round weights to tf32
__global__ void wprep_kernel(const float* __restrict__ Wih,
                             const float* __restrict__ Wout) {
    size_t idx = (size_t)blockIdx.x * 256 + threadIdx.x;
    const size_t NIH = (size_t)H3 * GIN;
    if (idx < NIH) g_wih[idx] = to_tf32(Wih[idx]);
    else           g_wout[idx - NIH] = to_tf32(Wout[idx - NIH]);
}

// ----------------------------- tf32 GEMM v2 (unchanged)
#define GSTG 36864
template<bool CAT, bool TANH>
__global__ void __launch_bounds__(256, 2)
gemm_v2(const float* __restrict__ A, const float* __restrict__ A2,
        const float* __restrict__ W, const float* __restrict__ bias,
        float* __restrict__ C, int N, int K) {
    extern __shared__ char smem[];
    const uint32_t sb = smem_u32(smem);
    const int tid  = threadIdx.x;
    const int lane = tid & 31;
    const int w    = tid >> 5;
    const int wm   = w >> 1;
    const int wn   = w & 1;
    const int bN   = blockIdx.x;
    const int bM   = blockIdx.y;
    const int S    = K >> 5;

    float acc[2][8][4];
#pragma unroll
    for (int mt = 0; mt < 2; ++mt)
#pragma unroll
        for (int nt = 0; nt < 8; ++nt)
#pragma unroll
            for (int i = 0; i < 4; ++i) acc[mt][nt][i] = 0.f;

    auto stage = [&](int s) {
        const int k0 = s * 32;
        const uint32_t base = sb + (uint32_t)(s % 3) * GSTG;
#pragma unroll
        for (int it = 0; it < 4; ++it) {
            int o = tid + it * 256;
            int row = o >> 3, seg = o & 7;
            size_t m = (size_t)bM * 128 + row;
            const float* srcA;
            if (CAT) {
                if (k0 < 1024) srcA = A  + m * 1024 + k0 + seg * 4;
                else           srcA = A2 + m * 1024 + (k0 - 1024) + seg * 4;
            } else {
                srcA = A + m * (size_t)K + k0 + seg * 4;
            }
            cpasync16(base + row * 144 + seg * 16, srcA);
            const float* srcB = W + ((size_t)bN * 128 + row) * (size_t)K + k0 + seg * 4;
            cpasync16(base + 18432 + row * 144 + seg * 16, srcB);
        }
        cp_commit();
    };

    stage(0); stage(1); stage(2);

    for (int s = 0; s < S; ++s) {
        asm volatile("cp.async.wait_group 2;" ::: "memory");
        __syncthreads();
        const uint32_t As = sb + (uint32_t)(s % 3) * GSTG;
        const uint32_t Bs = As + 18432;
        const uint32_t aAddr = As + (uint32_t)(wm * 32 + (lane & 15)) * 144 + (lane >> 4) * 16;
        const uint32_t bAddr = Bs + (uint32_t)(wn * 64 + (lane & 7)) * 144 + ((lane >> 3) & 1) * 16;
#pragma unroll
        for (int kk = 0; kk < 4; ++kk) {
            unsigned a[2][4], b[8][2];
#pragma unroll
            for (int mt = 0; mt < 2; ++mt)
                ldsm4(a[mt], aAddr + mt * 16 * 144 + kk * 32);
#pragma unroll
            for (int nt = 0; nt < 8; ++nt)
                ldsm2(b[nt], bAddr + nt * 8 * 144 + kk * 32);
#pragma unroll
            for (int mt = 0; mt < 2; ++mt)
#pragma unroll
                for (int nt = 0; nt < 8; ++nt)
                    mma_tf32(acc[mt][nt], a[mt], b[nt][0], b[nt][1]);
        }
        __syncthreads();
        if (s + 3 < S) stage(s + 3);
        else cp_commit();
    }

#pragma unroll
    for (int nt = 0; nt < 8; ++nt) {
        int col = bN * 128 + wn * 64 + nt * 8 + 2 * (lane & 3);
        float b0 = bias[col], b1 = bias[col + 1];
#pragma unroll
        for (int mt = 0; mt < 2; ++mt) {
            int row = bM * 128 + wm * 32 + mt * 16 + (lane >> 2);
            float v00 = acc[mt][nt][0] + b0;
            float v01 = acc[mt][nt][1] + b1;
            float v10 = acc[mt][nt][2] + b0;
            float v11 = acc[mt][nt][3] + b1;
            if (TANH) { v00 = tanhf(v00); v01 = tanhf(v01); v10 = tanhf(v10); v11 = tanhf(v11); }
            *(float2*)&C[(size_t)row * N + col]       = make_float2(v00, v01);
            *(float2*)&C[(size_t)(row + 8) * N + col] = make_float2(v10, v11);
        }
    }
}

// ----------------------------- GRU persistent kernel (R5 structure + fine-grained flags)
// 4 groups x 32 CTAs; group owns 16 batch rows; CTA owns 32 hidden cols.
// W slice 96x1024 fp16 B-frags SMEM-resident. h(t-1): 8 chunks of k=128,
// 3-buffer cp.async pipeline. Per-thread producer-flag acquire-poll inside
// stage(c): stage chunk as soon as ITS 4 producer CTAs published (no global
// group barrier). Epilogue publishes via bar.sync + tid0 st.release.
#define SM_W 0u
#define SM_A 196608u
#define ABUF 8704u
#define SM_P 196608u
#define SMEM_GRU 222720

__global__ void __launch_bounds__(384, 1)
gru_kernel(const float* __restrict__ Whh, const float* __restrict__ bhh,
           const int* __restrict__ x, const float* __restrict__ xproj,
           float* __restrict__ hall,
           __half* __restrict__ hhi, __half* __restrict__ hlo) {
    extern __shared__ char smem[];
    const uint32_t sb = smem_u32(smem);
    const int tid   = threadIdx.x;
    const int wid   = tid >> 5;
    const int lane  = tid & 31;
    const int group = blockIdx.x >> 5;        // 0..3
    const int b0    = group * 16;
    const int jc    = (blockIdx.x & 31) * 32; // 32 hidden cols
    const int gate  = wid >> 2;               // 0..2
    const int colofs = (wid & 3) * 8;         // 0,8,16,24

    // ---- one-time: pack W_hh slice (96 rows x 1024) into fp16 B-fragments
    for (int u = tid; u < 24576; u += 384) {
        int kt = u / 384;
        int rem = u % 384;
        int strip = rem >> 5, l = rem & 31;
        int g = strip >> 2, co = (strip & 3) * 8;
        int n = jc + co + (l >> 2);
        int k = kt * 16 + (l & 3) * 2;
        const float* wr = Whh + (size_t)(g * 1024 + n) * 1024;
        uint2 v;
        v.x = pk2h(__float2half_rn(wr[k]),     __float2half_rn(wr[k + 1]));
        v.y = pk2h(__float2half_rn(wr[k + 8]), __float2half_rn(wr[k + 9]));
        *(uint2*)(smem + SM_W + (size_t)(kt * 12 + strip) * 256 + (size_t)l * 8) = v;
    }
    __syncthreads();

    // ---- epilogue thread setup: tid<128, each owns (batch row, 4 cols)
    const int erow = tid >> 3;                // 0..15
    const int ec4  = (tid & 7) * 4;           // 0,4,..28
    const int eb   = b0 + erow;
    float hp[4] = {0.f, 0.f, 0.f, 0.f};
    float br_[4], bu_[4], bn_[4];
    if (tid < 128) {
#pragma unroll
        for (int j = 0; j < 4; ++j) {
            br_[j] = bhh[jc + ec4 + j];
            bu_[j] = bhh[1024 + jc + ec4 + j];
            bn_[j] = bhh[2048 + jc + ec4 + j];
        }
    }

    for (int t = 0; t < TT; ++t) {
        // ---- epilogue operand prefetch
        int xtok = 0;
        float4 xr, xu, xn;
        if (tid < 128) {
            xtok = x[eb * TT + t];
            const float* xb = xproj + ((size_t)eb * TT + t) * H3 + jc + ec4;
            xr = *(const float4*)xb;
            xu = *(const float4*)(xb + 1024);
            xn = *(const float4*)(xb + 2048);
        }

        if (t > 0) {
            // stage chunk c: per-thread acquire-poll on the ONE producer CTA
            // whose columns this thread copies, then cp.async. Deadlock-free:
            // flags are monotonic; step t needs only flags >= t (published
            // after step t-1); no cyclic dependency.
            auto stage = [&](int c) {
                if (tid < 256) {
                    int row = tid >> 4, seg = tid & 15;
                    const unsigned* f =
                        &g_flags[(group * 32 + c * 4 + (seg >> 2)) * 8];
                    unsigned v;
                    for (;;) {
                        asm volatile("ld.acquire.gpu.global.u32 %0, [%1];"
                                     : "=r"(v) : "l"(f));
                        if (v >= (unsigned)t) break;
                        __nanosleep(20);
                    }
                    size_t so = ((size_t)(t - 1) * BB + b0 + row) * HID + c * 128 + seg * 8;
                    uint32_t dst = sb + SM_A + (uint32_t)(c % 3) * ABUF
                                 + (uint32_t)row * 272 + seg * 16;
                    cpasync16(dst, hhi + so);
                    cpasync16(dst + 4352, hlo + so);
                }
                cp_commit();
            };

            float aH[2][4] = {}, aL[2][4] = {};
            stage(0); stage(1);
            for (int c = 0; c < 8; ++c) {
                if (c < 7) asm volatile("cp.async.wait_group 1;" ::: "memory");
                else       asm volatile("cp.async.wait_group 0;" ::: "memory");
                __syncthreads();
                if (c < 6) stage(c + 2);
                const uint32_t ah = sb + SM_A + (uint32_t)(c % 3) * ABUF
                                  + (uint32_t)(lane & 15) * 272 + (lane >> 4) * 16;
#pragma unroll
                for (int kt = 0; kt < 8; ++kt) {
                    unsigned hiF[4], loF[4];
                    ldsm4(hiF, ah + kt * 32);
                    ldsm4(loF, ah + 4352 + kt * 32);
                    uint2 B = *(const uint2*)(smem + SM_W
                              + (size_t)((c * 8 + kt) * 12 + wid) * 256 + (size_t)lane * 8);
                    const int p = kt & 1;
                    mma_f16(aH[p], hiF, B.x, B.y);
                    mma_f16(aL[p], loF, B.x, B.y);
                }
            }
            float ds[4];
#pragma unroll
            for (int i = 0; i < 4; ++i)
                ds[i] = aH[0][i] + aH[1][i] + aL[0][i] + aL[1][i];
            // preact write: [gate][16 rows][36 floats] (aliases A buffer 0;
            // safe: buf0 last read at chunk 6, ordered before sync(7))
            {
                int r = lane >> 2;
                int col = colofs + 2 * (lane & 3);
                *(float2*)(smem + SM_P + (size_t)(gate * 16 + r) * 144 + (size_t)col * 4)
                    = make_float2(ds[0], ds[1]);
                *(float2*)(smem + SM_P + (size_t)(gate * 16 + r + 8) * 144 + (size_t)col * 4)
                    = make_float2(ds[2], ds[3]);
            }
        }
        __syncthreads();

        // ---- epilogue: 128 threads, (row, 4 cols) each
        if (tid < 128) {
            float dr[4] = {}, du[4] = {}, dn[4] = {};
            if (t > 0) {
                float4 v0 = *(const float4*)(smem + SM_P + (size_t)erow * 144 + ec4 * 4);
                float4 v1 = *(const float4*)(smem + SM_P + (size_t)(16 + erow) * 144 + ec4 * 4);
                float4 v2 = *(const float4*)(smem + SM_P + (size_t)(32 + erow) * 144 + ec4 * 4);
                dr[0] = v0.x; dr[1] = v0.y; dr[2] = v0.z; dr[3] = v0.w;
                du[0] = v1.x; du[1] = v1.y; du[2] = v1.z; du[3] = v1.w;
                dn[0] = v2.x; dn[1] = v2.y; dn[2] = v2.z; dn[3] = v2.w;
            }
            float xrv[4] = {xr.x, xr.y, xr.z, xr.w};
            float xuv[4] = {xu.x, xu.y, xu.z, xu.w};
            float xnv[4] = {xn.x, xn.y, xn.z, xn.w};
            const bool msk = (xtok == 0);   // PAD
            float hv[4];
#pragma unroll
            for (int j = 0; j < 4; ++j) {
                float rr = sigmoidf(xrv[j] + dr[j] + br_[j]);
                float uu = sigmoidf(xuv[j] + du[j] + bu_[j]);
                float nn = tanhf(xnv[j] + rr * (dn[j] + bn_[j]));
                float h  = (1.f - uu) * nn + uu * hp[j];
                hv[j] = msk ? hp[j] : h;
                hp[j] = hv[j];
            }
            // hall (tf32-rounded)
            *(float4*)(hall + ((size_t)eb * TT + t) * HID + jc + ec4)
                = make_float4(to_tf32(hv[0]), to_tf32(hv[1]), to_tf32(hv[2]), to_tf32(hv[3]));
            // fp16 hi/lo for next step
            __half hb[4], lb[4];
#pragma unroll
            for (int j = 0; j < 4; ++j) {
                hb[j] = __float2half_rn(hv[j]);
                lb[j] = __float2half_rn(hv[j] - __half2float(hb[j]));
            }
            uint2 uh, ul;
            uh.x = pk2h(hb[0], hb[1]); uh.y = pk2h(hb[2], hb[3]);
            ul.x = pk2h(lb[0], lb[1]); ul.y = pk2h(lb[2], lb[3]);
            *(uint2*)(hhi + ((size_t)t * BB + eb) * HID + jc + ec4) = uh;
            *(uint2*)(hlo + ((size_t)t * BB + eb) * HID + jc + ec4) = ul;
        }
        __syncthreads();

        // ---- publish: bar gives intra-CTA HB; release store publishes at gpu
        // scope (hb transitivity: epilogue writes -> bar -> release).
        if (tid == 0) {
            asm volatile("st.release.gpu.global.u32 [%0], %1;"
                         :: "l"(&g_flags[blockIdx.x * 8]), "r"((unsigned)(t + 1)) : "memory");
        }
    }
}

// ----------------------------- launch
extern "C" void kernel_launch(void* const* d_in, const int* in_sizes, int n_in,
                              void* d_out, int out_size) {
    const int*   x     = (const int*)d_in[0];
    const float* z     = (const float*)d_in[1];
    const float* emb   = (const float*)d_in[2];
    const float* W_ih  = (const float*)d_in[3];
    const float* b_ih  = (const float*)d_in[4];
    const float* W_hh  = (const float*)d_in[5];
    const float* b_hh  = (const float*)d_in[6];
    const float* W_out = (const float*)d_in[7];
    const float* b_out = (const float*)d_in[8];
    float* out = (float*)d_out;

    float *inp_p, *xproj_p, *hall_p, *wih_p, *wout_p;
    __half *hhi_p, *hlo_p;
    cudaGetSymbolAddress((void**)&inp_p,   g_inp);
    cudaGetSymbolAddress((void**)&xproj_p, g_xproj);
    cudaGetSymbolAddress((void**)&hall_p,  g_hall);
    cudaGetSymbolAddress((void**)&wih_p,   g_wih);
    cudaGetSymbolAddress((void**)&wout_p,  g_wout);
    cudaGetSymbolAddress((void**)&hhi_p,   g_hhi);
    cudaGetSymbolAddress((void**)&hlo_p,   g_hlo);

    // 1. build inp (tf32'd emb||z), reset barrier flags
    build_inp_kernel<<<(unsigned)((size_t)BT * GIN / 256), 256>>>(x, z, emb);

    // 2. tf32-round weights
    wprep_kernel<<<(unsigned)(((size_t)H3 * GIN + (size_t)NIN * KOUT) / 256), 256>>>(W_ih, W_out);

    // 3. x_proj = inp @ W_ih^T + b_ih   [32768 x 3072], K=1024
    {
        cudaFuncSetAttribute(gemm_v2<false, false>,
                             cudaFuncAttributeMaxDynamicSharedMemorySize, 3 * GSTG);
        dim3 grid(H3 / 128, BT / 128);
        gemm_v2<false, false><<<grid, 256, 3 * GSTG>>>(
            inp_p, nullptr, wih_p, b_ih, xproj_p, H3, GIN);
    }

    // 4. GRU recurrence: 4 independent batch groups x 32 CTAs
    {
        cudaFuncSetAttribute(gru_kernel,
                             cudaFuncAttributeMaxDynamicSharedMemorySize, SMEM_GRU);
        gru_kernel<<<128, 384, SMEM_GRU>>>(W_hh, b_hh, x, xproj_p, hall_p, hhi_p, hlo_p);
    }

    // 5. logits = tanh([hidden|emb] @ W_out^T + b_out)   [32768 x 512], K=1536
    {
        cudaFuncSetAttribute(gemm_v2<true, true>,
                             cudaFuncAttributeMaxDynamicSharedMemorySize, 3 * GSTG);
        dim3 grid(NIN / 128, BT / 128);
        gemm_v2<true, true><<<grid, 256, 3 * GSTG>>>(
            hall_p, inp_p, wout_p, b_out, out, NIN, KOUT);
    }
}

// round 8
// speedup vs baseline: 1.7121x; 1.7121x over previous
#include <cuda_runtime.h>
#include <cuda_bf16.h>
#include <cuda_fp16.h>
#include <cstdint>

// Problem constants
#define BB 64
#define TT 512
#define BT (BB*TT)          // 32768
#define GIN 1024
#define HID 1024
#define H3  3072
#define NIN 512
#define KOUT 1536

// ----------------------------- scratch (device globals)
__device__ float g_inp[(size_t)BT * GIN];                  // tf32-rounded [emb|z]
__device__ float g_xproj[(size_t)BT * H3];
__device__ float g_hall[(size_t)BT * HID];                 // tf32-rounded h, [b][t][H]
__device__ __half g_hhi[(size_t)TT * BB * HID];            // [t][b][H] fp16 h
__device__ float g_wih[(size_t)H3 * GIN];                  // tf32-rounded W_ih
__device__ float g_wout[(size_t)NIN * KOUT];               // tf32-rounded W_out
__device__ unsigned g_flags[128 * 8];                      // flags (32B apart)

// ----------------------------- helpers
__device__ __forceinline__ float to_tf32(float x) {
    unsigned u;
    asm("cvt.rna.tf32.f32 %0, %1;" : "=r"(u) : "f"(x));
    return __uint_as_float(u);
}
__device__ __forceinline__ void mma_tf32(float acc[4], const unsigned a[4],
                                         unsigned b0, unsigned b1) {
    asm volatile(
        "mma.sync.aligned.m16n8k8.row.col.f32.tf32.tf32.f32 "
        "{%0,%1,%2,%3},{%4,%5,%6,%7},{%8,%9},{%0,%1,%2,%3};"
        : "+f"(acc[0]), "+f"(acc[1]), "+f"(acc[2]), "+f"(acc[3])
        : "r"(a[0]), "r"(a[1]), "r"(a[2]), "r"(a[3]), "r"(b0), "r"(b1));
}
__device__ __forceinline__ void mma_f16(float acc[4], const unsigned a[4],
                                        unsigned b0, unsigned b1) {
    asm volatile(
        "mma.sync.aligned.m16n8k16.row.col.f32.f16.f16.f32 "
        "{%0,%1,%2,%3},{%4,%5,%6,%7},{%8,%9},{%0,%1,%2,%3};"
        : "+f"(acc[0]), "+f"(acc[1]), "+f"(acc[2]), "+f"(acc[3])
        : "r"(a[0]), "r"(a[1]), "r"(a[2]), "r"(a[3]), "r"(b0), "r"(b1));
}
__device__ __forceinline__ void ldsm4(unsigned r[4], uint32_t addr) {
    asm volatile("ldmatrix.sync.aligned.m8n8.x4.shared.b16 {%0,%1,%2,%3}, [%4];"
                 : "=r"(r[0]), "=r"(r[1]), "=r"(r[2]), "=r"(r[3]) : "r"(addr));
}
__device__ __forceinline__ void ldsm2(unsigned r[2], uint32_t addr) {
    asm volatile("ldmatrix.sync.aligned.m8n8.x2.shared.b16 {%0,%1}, [%2];"
                 : "=r"(r[0]), "=r"(r[1]) : "r"(addr));
}
__device__ __forceinline__ uint32_t smem_u32(const void* p) {
    uint32_t a;
    asm("{ .reg .u64 t; cvta.to.shared.u64 t, %1; cvt.u32.u64 %0, t; }" : "=r"(a) : "l"(p));
    return a;
}
__device__ __forceinline__ void cpasync16(uint32_t dst, const void* src) {
    asm volatile("cp.async.cg.shared.global [%0], [%1], 16;" :: "r"(dst), "l"(src) : "memory");
}
__device__ __forceinline__ void cp_commit() {
    asm volatile("cp.async.commit_group;" ::: "memory");
}
__device__ __forceinline__ float sigmoidf(float v) { return 1.0f / (1.0f + expf(-v)); }
__device__ __forceinline__ uint32_t pk2h(__half a, __half b) {
    __half2 t(a, b);
    return *(uint32_t*)&t;
}

// ----------------------------- kernel: gather emb + concat z (tf32) ; reset flags
__global__ void build_inp_kernel(const int* __restrict__ x,
                                 const float* __restrict__ z,
                                 const float* __restrict__ emb) {
    size_t idx = (size_t)blockIdx.x * 256 + threadIdx.x;
    if (idx < 1024) g_flags[idx] = 0u;
    int m = (int)(idx >> 10);
    int k = (int)(idx & 1023);
    int b = m >> 9;
    float v;
    if (k < 512) v = emb[(size_t)x[m] * 512 + k];
    else         v = z[b * 512 + (k - 512)];
    g_inp[idx] = to_tf32(v);
}

// ----------------------------- kernel: pre-round weights to tf32
__global__ void wprep_kernel(const float* __restrict__ Wih,
                             const float* __restrict__ Wout) {
    size_t idx = (size_t)blockIdx.x * 256 + threadIdx.x;
    const size_t NIH = (size_t)H3 * GIN;
    if (idx < NIH) g_wih[idx] = to_tf32(Wih[idx]);
    else           g_wout[idx - NIH] = to_tf32(Wout[idx - NIH]);
}

// ----------------------------- tf32 GEMM v2 (unchanged)
#define GSTG 36864
template<bool CAT, bool TANH>
__global__ void __launch_bounds__(256, 2)
gemm_v2(const float* __restrict__ A, const float* __restrict__ A2,
        const float* __restrict__ W, const float* __restrict__ bias,
        float* __restrict__ C, int N, int K) {
    extern __shared__ char smem[];
    const uint32_t sb = smem_u32(smem);
    const int tid  = threadIdx.x;
    const int lane = tid & 31;
    const int w    = tid >> 5;
    const int wm   = w >> 1;
    const int wn   = w & 1;
    const int bN   = blockIdx.x;
    const int bM   = blockIdx.y;
    const int S    = K >> 5;

    float acc[2][8][4];
#pragma unroll
    for (int mt = 0; mt < 2; ++mt)
#pragma unroll
        for (int nt = 0; nt < 8; ++nt)
#pragma unroll
            for (int i = 0; i < 4; ++i) acc[mt][nt][i] = 0.f;

    auto stage = [&](int s) {
        const int k0 = s * 32;
        const uint32_t base = sb + (uint32_t)(s % 3) * GSTG;
#pragma unroll
        for (int it = 0; it < 4; ++it) {
            int o = tid + it * 256;
            int row = o >> 3, seg = o & 7;
            size_t m = (size_t)bM * 128 + row;
            const float* srcA;
            if (CAT) {
                if (k0 < 1024) srcA = A  + m * 1024 + k0 + seg * 4;
                else           srcA = A2 + m * 1024 + (k0 - 1024) + seg * 4;
            } else {
                srcA = A + m * (size_t)K + k0 + seg * 4;
            }
            cpasync16(base + row * 144 + seg * 16, srcA);
            const float* srcB = W + ((size_t)bN * 128 + row) * (size_t)K + k0 + seg * 4;
            cpasync16(base + 18432 + row * 144 + seg * 16, srcB);
        }
        cp_commit();
    };

    stage(0); stage(1); stage(2);

    for (int s = 0; s < S; ++s) {
        asm volatile("cp.async.wait_group 2;" ::: "memory");
        __syncthreads();
        const uint32_t As = sb + (uint32_t)(s % 3) * GSTG;
        const uint32_t Bs = As + 18432;
        const uint32_t aAddr = As + (uint32_t)(wm * 32 + (lane & 15)) * 144 + (lane >> 4) * 16;
        const uint32_t bAddr = Bs + (uint32_t)(wn * 64 + (lane & 7)) * 144 + ((lane >> 3) & 1) * 16;
#pragma unroll
        for (int kk = 0; kk < 4; ++kk) {
            unsigned a[2][4], b[8][2];
#pragma unroll
            for (int mt = 0; mt < 2; ++mt)
                ldsm4(a[mt], aAddr + mt * 16 * 144 + kk * 32);
#pragma unroll
            for (int nt = 0; nt < 8; ++nt)
                ldsm2(b[nt], bAddr + nt * 8 * 144 + kk * 32);
#pragma unroll
            for (int mt = 0; mt < 2; ++mt)
#pragma unroll
                for (int nt = 0; nt < 8; ++nt)
                    mma_tf32(acc[mt][nt], a[mt], b[nt][0], b[nt][1]);
        }
        __syncthreads();
        if (s + 3 < S) stage(s + 3);
        else cp_commit();
    }

#pragma unroll
    for (int nt = 0; nt < 8; ++nt) {
        int col = bN * 128 + wn * 64 + nt * 8 + 2 * (lane & 3);
        float b0 = bias[col], b1 = bias[col + 1];
#pragma unroll
        for (int mt = 0; mt < 2; ++mt) {
            int row = bM * 128 + wm * 32 + mt * 16 + (lane >> 2);
            float v00 = acc[mt][nt][0] + b0;
            float v01 = acc[mt][nt][1] + b1;
            float v10 = acc[mt][nt][2] + b0;
            float v11 = acc[mt][nt][3] + b1;
            if (TANH) { v00 = tanhf(v00); v01 = tanhf(v01); v10 = tanhf(v10); v11 = tanhf(v11); }
            *(float2*)&C[(size_t)row * N + col]       = make_float2(v00, v01);
            *(float2*)&C[(size_t)(row + 8) * N + col] = make_float2(v10, v11);
        }
    }
}

// ----------------------------- GRU persistent kernel v3
// 4 groups x 32 CTAs; group owns 16 batch rows; CTA owns 32 hidden cols.
// h stored as SINGLE fp16 (hp stays fp32 in registers; the fp16 store only
// perturbs the matmul input — damped by the u-gate, steady-state ~3e-5).
// 12 warps: warp = (gate = wid>>2, kh = (wid>>1)&1, ch = wid&1):
//   M=16 rows, N=16 cols (ch half), K=512 (kh half) -> 4 chunk-pair iters.
// Stage PAIRS {i, i+4} (k=128 each) into 3 rotating pair-buffers.
// Preact partials [3][2][16][36]f alias pair-buffers 1..2 (free after bar(3)).
#define SM_W 0u
#define SM_A 196608u
#define PBUF 8704u
#define SM_P (196608u + 8704u)
#define SMEM_GRU 222720

__global__ void __launch_bounds__(384, 1)
gru_kernel(const float* __restrict__ Whh, const float* __restrict__ bhh,
           const int* __restrict__ x, const float* __restrict__ xproj,
           float* __restrict__ hall, __half* __restrict__ hhi) {
    extern __shared__ char smem[];
    const uint32_t sb = smem_u32(smem);
    const int tid   = threadIdx.x;
    const int wid   = tid >> 5;
    const int lane  = tid & 31;
    const int group = blockIdx.x >> 5;        // 0..3
    const int b0    = group * 16;
    const int jc    = (blockIdx.x & 31) * 32; // 32 hidden cols
    const int gate  = wid >> 2;               // 0..2
    const int kh    = (wid >> 1) & 1;         // k-half
    const int ch    = wid & 1;                // col-half
    const int s0    = gate * 4 + ch * 2;      // W strip ids
    const int s1    = s0 + 1;

    // ---- one-time: pack W_hh slice (96 rows x 1024) into fp16 B-fragments
    // layout: [64 kt][12 strips][32 lanes x uint2]; strip covers cols (strip&3)*8
    for (int u = tid; u < 24576; u += 384) {
        int kt = u / 384;
        int rem = u % 384;
        int strip = rem >> 5, l = rem & 31;
        int g = strip >> 2, co = (strip & 3) * 8;
        int n = jc + co + (l >> 2);
        int k = kt * 16 + (l & 3) * 2;
        const float* wr = Whh + (size_t)(g * 1024 + n) * 1024;
        uint2 v;
        v.x = pk2h(__float2half_rn(wr[k]),     __float2half_rn(wr[k + 1]));
        v.y = pk2h(__float2half_rn(wr[k + 8]), __float2half_rn(wr[k + 9]));
        *(uint2*)(smem + SM_W + (size_t)(kt * 12 + strip) * 256 + (size_t)l * 8) = v;
    }
    __syncthreads();

    // ---- epilogue thread setup: tid<128, each owns (batch row, 4 cols)
    const int erow = tid >> 3;                // 0..15
    const int ec4  = (tid & 7) * 4;           // 0,4,..28
    const int eb   = b0 + erow;
    float hp[4] = {0.f, 0.f, 0.f, 0.f};
    float br_[4], bu_[4], bn_[4];
    if (tid < 128) {
#pragma unroll
        for (int j = 0; j < 4; ++j) {
            br_[j] = bhh[jc + ec4 + j];
            bu_[j] = bhh[1024 + jc + ec4 + j];
            bn_[j] = bhh[2048 + jc + ec4 + j];
        }
    }

    for (int t = 0; t < TT; ++t) {
        // ---- epilogue operand prefetch (DRAM latency overlaps flag poll)
        int xtok = 0;
        float4 xr, xu, xn;
        if (tid < 128) {
            xtok = x[eb * TT + t];
            const float* xb = xproj + ((size_t)eb * TT + t) * H3 + jc + ec4;
            xr = *(const float4*)xb;
            xu = *(const float4*)(xb + 1024);
            xn = *(const float4*)(xb + 2048);
        }

        if (t > 0) {
            // coarse group-flag wait: warp 0, one flag per lane
            if (wid == 0) {
                const unsigned* f = &g_flags[(group * 32 + lane) * 8];
                for (;;) {
                    unsigned v;
                    asm volatile("ld.acquire.gpu.global.u32 %0, [%1];" : "=r"(v) : "l"(f));
                    if (__all_sync(0xffffffffu, v >= (unsigned)t)) break;
                    __nanosleep(20);
                }
            }
            __syncthreads();

            // stage pair i: chunks {i, i+4} of h(t-1), fp16 single plane
            auto stage = [&](int i) {
                if (tid < 256) {
                    int row = tid >> 4, seg = tid & 15;
                    const __half* src = hhi + ((size_t)(t - 1) * BB + b0 + row) * HID + seg * 8;
                    uint32_t dst = sb + SM_A + (uint32_t)(i % 3) * PBUF
                                 + (uint32_t)row * 272 + seg * 16;
                    cpasync16(dst,        src + i * 128);
                    cpasync16(dst + 4352, src + (i + 4) * 128);
                }
                cp_commit();
            };

            float acc[2][2][4] = {};   // [ntile][parity][4]
            stage(0); stage(1);
            for (int i = 0; i < 4; ++i) {
                if (i < 3) asm volatile("cp.async.wait_group 1;" ::: "memory");
                else       asm volatile("cp.async.wait_group 0;" ::: "memory");
                __syncthreads();
                if (i < 2) stage(i + 2);
                const uint32_t ah = sb + SM_A + (uint32_t)(i % 3) * PBUF
                                  + (uint32_t)kh * 4352
                                  + (uint32_t)(lane & 15) * 272 + (lane >> 4) * 16;
                const int ktg0 = kh * 32 + i * 8;
#pragma unroll
                for (int kt = 0; kt < 8; ++kt) {
                    unsigned aF[4];
                    ldsm4(aF, ah + kt * 32);
                    uint2 B0 = *(const uint2*)(smem + SM_W
                               + (size_t)((ktg0 + kt) * 12 + s0) * 256 + (size_t)lane * 8);
                    uint2 B1 = *(const uint2*)(smem + SM_W
                               + (size_t)((ktg0 + kt) * 12 + s1) * 256 + (size_t)lane * 8);
                    const int p = kt & 1;
                    mma_f16(acc[0][p], aF, B0.x, B0.y);
                    mma_f16(acc[1][p], aF, B1.x, B1.y);
                }
            }
            // preact partial write: [(gate*2+kh)*16 + r][36 floats]
            {
                int r  = lane >> 2;
                int cb = ch * 16 + 2 * (lane & 3);
#pragma unroll
                for (int nt = 0; nt < 2; ++nt) {
                    float d0 = acc[nt][0][0] + acc[nt][1][0];
                    float d1 = acc[nt][0][1] + acc[nt][1][1];
                    float d2 = acc[nt][0][2] + acc[nt][1][2];
                    float d3 = acc[nt][0][3] + acc[nt][1][3];
                    int col = cb + nt * 8;
                    *(float2*)(smem + SM_P
                        + (size_t)(((gate * 2 + kh) * 16 + r) * 36 + col) * 4)
                        = make_float2(d0, d1);
                    *(float2*)(smem + SM_P
                        + (size_t)(((gate * 2 + kh) * 16 + r + 8) * 36 + col) * 4)
                        = make_float2(d2, d3);
                }
            }
        }
        __syncthreads();

        // ---- epilogue: 128 threads, (row, 4 cols) each
        float hv[4];
        if (tid < 128) {
            float dr[4] = {}, du[4] = {}, dn[4] = {};
            if (t > 0) {
#pragma unroll
                for (int g = 0; g < 3; ++g) {
                    float4 a = *(const float4*)(smem + SM_P
                               + (size_t)((g * 2 + 0) * 16 + erow) * 144 + ec4 * 4);
                    float4 b = *(const float4*)(smem + SM_P
                               + (size_t)((g * 2 + 1) * 16 + erow) * 144 + ec4 * 4);
                    float* d = (g == 0) ? dr : (g == 1 ? du : dn);
                    d[0] = a.x + b.x; d[1] = a.y + b.y;
                    d[2] = a.z + b.z; d[3] = a.w + b.w;
                }
            }
            float xrv[4] = {xr.x, xr.y, xr.z, xr.w};
            float xuv[4] = {xu.x, xu.y, xu.z, xu.w};
            float xnv[4] = {xn.x, xn.y, xn.z, xn.w};
            const bool msk = (xtok == 0);   // PAD
#pragma unroll
            for (int j = 0; j < 4; ++j) {
                float rr = sigmoidf(xrv[j] + dr[j] + br_[j]);
                float uu = sigmoidf(xuv[j] + du[j] + bu_[j]);
                float nn = tanhf(xnv[j] + rr * (dn[j] + bn_[j]));
                float h  = (1.f - uu) * nn + uu * hp[j];
                hv[j] = msk ? hp[j] : h;
                hp[j] = hv[j];
            }
            // publish fp16 h FIRST (critical path)
            uint2 uh;
            uh.x = pk2h(__float2half_rn(hv[0]), __float2half_rn(hv[1]));
            uh.y = pk2h(__float2half_rn(hv[2]), __float2half_rn(hv[3]));
            *(uint2*)(hhi + ((size_t)t * BB + eb) * HID + jc + ec4) = uh;
        }
        __syncthreads();

        // ---- release (bar gives intra-CTA HB; gpu-scope release publishes)
        if (tid == 0) {
            asm volatile("st.release.gpu.global.u32 [%0], %1;"
                         :: "l"(&g_flags[blockIdx.x * 8]), "r"((unsigned)(t + 1)) : "memory");
        }
        // hall store off the critical path (only read by out-GEMM post-kernel)
        if (tid < 128) {
            *(float4*)(hall + ((size_t)eb * TT + t) * HID + jc + ec4)
                = make_float4(to_tf32(hv[0]), to_tf32(hv[1]),
                              to_tf32(hv[2]), to_tf32(hv[3]));
        }
    }
}

// ----------------------------- launch
extern "C" void kernel_launch(void* const* d_in, const int* in_sizes, int n_in,
                              void* d_out, int out_size) {
    const int*   x     = (const int*)d_in[0];
    const float* z     = (const float*)d_in[1];
    const float* emb   = (const float*)d_in[2];
    const float* W_ih  = (const float*)d_in[3];
    const float* b_ih  = (const float*)d_in[4];
    const float* W_hh  = (const float*)d_in[5];
    const float* b_hh  = (const float*)d_in[6];
    const float* W_out = (const float*)d_in[7];
    const float* b_out = (const float*)d_in[8];
    float* out = (float*)d_out;

    float *inp_p, *xproj_p, *hall_p, *wih_p, *wout_p;
    __half *hhi_p;
    cudaGetSymbolAddress((void**)&inp_p,   g_inp);
    cudaGetSymbolAddress((void**)&xproj_p, g_xproj);
    cudaGetSymbolAddress((void**)&hall_p,  g_hall);
    cudaGetSymbolAddress((void**)&wih_p,   g_wih);
    cudaGetSymbolAddress((void**)&wout_p,  g_wout);
    cudaGetSymbolAddress((void**)&hhi_p,   g_hhi);

    // 1. build inp (tf32'd emb||z), reset barrier flags
    build_inp_kernel<<<(unsigned)((size_t)BT * GIN / 256), 256>>>(x, z, emb);

    // 2. tf32-round weights
    wprep_kernel<<<(unsigned)(((size_t)H3 * GIN + (size_t)NIN * KOUT) / 256), 256>>>(W_ih, W_out);

    // 3. x_proj = inp @ W_ih^T + b_ih   [32768 x 3072], K=1024
    {
        cudaFuncSetAttribute(gemm_v2<false, false>,
                             cudaFuncAttributeMaxDynamicSharedMemorySize, 3 * GSTG);
        dim3 grid(H3 / 128, BT / 128);
        gemm_v2<false, false><<<grid, 256, 3 * GSTG>>>(
            inp_p, nullptr, wih_p, b_ih, xproj_p, H3, GIN);
    }

    // 4. GRU recurrence: 4 independent batch groups x 32 CTAs
    {
        cudaFuncSetAttribute(gru_kernel,
                             cudaFuncAttributeMaxDynamicSharedMemorySize, SMEM_GRU);
        gru_kernel<<<128, 384, SMEM_GRU>>>(W_hh, b_hh, x, xproj_p, hall_p, hhi_p);
    }

    // 5. logits = tanh([hidden|emb] @ W_out^T + b_out)   [32768 x 512], K=1536
    {
        cudaFuncSetAttribute(gemm_v2<true, true>,
                             cudaFuncAttributeMaxDynamicSharedMemorySize, 3 * GSTG);
        dim3 grid(NIN / 128, BT / 128);
        gemm_v2<true, true><<<grid, 256, 3 * GSTG>>>(
            hall_p, inp_p, wout_p, b_out, out, NIN, KOUT);
    }
}

// round 9
// speedup vs baseline: 2.1759x; 1.2709x over previous
#include <cuda_runtime.h>
#include <cuda_bf16.h>
#include <cuda_fp16.h>
#include <cstdint>

// Problem constants
#define BB 64
#define TT 512
#define BT (BB*TT)          // 32768
#define GIN 1024
#define HID 1024
#define H3  3072
#define NIN 512
#define KOUT 1536

// ----------------------------- scratch (device globals)
__device__ __half g_inp[(size_t)BT * GIN];                 // fp16 [emb|z]
__device__ float g_xproj[(size_t)BT * H3];
__device__ __half g_hhi[(size_t)TT * BB * HID];            // [t][b][H] fp16 h
__device__ uint2 g_wihp[786432];                           // W_ih fp16 frag-packed
__device__ uint2 g_woutp[196608];                          // W_out fp16 frag-packed
__device__ unsigned g_flags[128 * 8];                      // flags (32B apart)

// ----------------------------- helpers
__device__ __forceinline__ void mma_f16(float acc[4], const unsigned a[4],
                                        unsigned b0, unsigned b1) {
    asm volatile(
        "mma.sync.aligned.m16n8k16.row.col.f32.f16.f16.f32 "
        "{%0,%1,%2,%3},{%4,%5,%6,%7},{%8,%9},{%0,%1,%2,%3};"
        : "+f"(acc[0]), "+f"(acc[1]), "+f"(acc[2]), "+f"(acc[3])
        : "r"(a[0]), "r"(a[1]), "r"(a[2]), "r"(a[3]), "r"(b0), "r"(b1));
}
__device__ __forceinline__ void ldsm4(unsigned r[4], uint32_t addr) {
    asm volatile("ldmatrix.sync.aligned.m8n8.x4.shared.b16 {%0,%1,%2,%3}, [%4];"
                 : "=r"(r[0]), "=r"(r[1]), "=r"(r[2]), "=r"(r[3]) : "r"(addr));
}
__device__ __forceinline__ uint32_t smem_u32(const void* p) {
    uint32_t a;
    asm("{ .reg .u64 t; cvta.to.shared.u64 t, %1; cvt.u32.u64 %0, t; }" : "=r"(a) : "l"(p));
    return a;
}
__device__ __forceinline__ void cpasync16(uint32_t dst, const void* src) {
    asm volatile("cp.async.cg.shared.global [%0], [%1], 16;" :: "r"(dst), "l"(src) : "memory");
}
__device__ __forceinline__ void cp_commit() {
    asm volatile("cp.async.commit_group;" ::: "memory");
}
__device__ __forceinline__ float sigmoidf(float v) { return 1.0f / (1.0f + expf(-v)); }
__device__ __forceinline__ uint32_t pk2h(__half a, __half b) {
    __half2 t(a, b);
    return *(uint32_t*)&t;
}

// ----------------------------- kernel: gather emb + concat z (fp16) ; reset flags
__global__ void build_inp_kernel(const int* __restrict__ x,
                                 const float* __restrict__ z,
                                 const float* __restrict__ emb) {
    size_t idx = (size_t)blockIdx.x * 256 + threadIdx.x;
    if (idx < 1024) g_flags[idx] = 0u;
    int m = (int)(idx >> 10);
    int k = (int)(idx & 1023);
    int b = m >> 9;
    float v;
    if (k < 512) v = emb[(size_t)x[m] * 512 + k];
    else         v = z[b * 512 + (k - 512)];
    g_inp[idx] = __float2half_rn(v);
}

// ----------------------------- kernel: pack weights into fp16 B-fragment order
// layout: per (kt, n-strip): 32 lanes x uint2; lane l: n = strip*8+(l>>2),
// k = kt*16+(l&3)*2; v = {w[k],w[k+1] | w[k+8],w[k+9]}.
__global__ void wpack_kernel(const float* __restrict__ Wih,
                             const float* __restrict__ Wout) {
    int idx = blockIdx.x * 256 + threadIdx.x;
    if (idx < 786432) {
        int kt = idx / 12288;           // 384*32
        int r  = idx % 12288;
        int strip = r >> 5, l = r & 31;
        int n = strip * 8 + (l >> 2);
        int k = kt * 16 + (l & 3) * 2;
        const float* wr = Wih + (size_t)n * GIN + k;
        uint2 v;
        v.x = pk2h(__float2half_rn(wr[0]), __float2half_rn(wr[1]));
        v.y = pk2h(__float2half_rn(wr[8]), __float2half_rn(wr[9]));
        g_wihp[idx] = v;
    } else {
        int j  = idx - 786432;          // < 196608
        int kt = j / 2048;              // 64*32
        int r  = j % 2048;
        int strip = r >> 5, l = r & 31;
        int n = strip * 8 + (l >> 2);
        int k = kt * 16 + (l & 3) * 2;
        const float* wr = Wout + (size_t)n * KOUT + k;
        uint2 v;
        v.x = pk2h(__float2half_rn(wr[0]), __float2half_rn(wr[1]));
        v.y = pk2h(__float2half_rn(wr[8]), __float2half_rn(wr[9]));
        g_woutp[j] = v;
    }
}

// ----------------------------- fp16 GEMM: C[M,N] = A[M,K]*W[N,K]^T + bias
// 128x128 CTA tile, 8 warps (32x64 warp tile), 3-stage k64 cp.async pipeline.
// B arrives frag-packed (per kt: 16 strips x 256B) -> direct uint2 reads.
// CAT: k<1024 from hidden g_hhi ([t][b][H] indexing), k>=1024 from inp emb.
#define FSTG 34816              // A 128*144 + B 16384
template<bool CAT, bool TANH>
__global__ void __launch_bounds__(256, 2)
gemm_f16(const __half* __restrict__ Ainp, const __half* __restrict__ Ahid,
         const uint2* __restrict__ Wp, const float* __restrict__ bias,
         float* __restrict__ C, int N, int K) {
    extern __shared__ char smem[];
    const uint32_t sb = smem_u32(smem);
    const int tid  = threadIdx.x;
    const int lane = tid & 31;
    const int w    = tid >> 5;
    const int wm   = w >> 1;        // 0..3
    const int wn   = w & 1;         // 0..1
    const int bN   = blockIdx.x;
    const int bM   = blockIdx.y;
    const int S    = K >> 6;        // k64 stages
    const int NSTRIP = N >> 3;

    float acc[2][8][4];
#pragma unroll
    for (int mt = 0; mt < 2; ++mt)
#pragma unroll
        for (int nt = 0; nt < 8; ++nt)
#pragma unroll
            for (int i = 0; i < 4; ++i) acc[mt][nt][i] = 0.f;

    auto stage = [&](int s) {
        const int k0 = s * 64;
        const uint32_t base = sb + (uint32_t)(s % 3) * FSTG;
        // A tile: 128 rows x 64 halves (8 segs of 16B), row stride 144B
#pragma unroll
        for (int it = 0; it < 4; ++it) {
            int o = tid + it * 256;
            int row = o >> 3, seg = o & 7;
            int m = bM * 128 + row;
            const __half* srcA;
            if (CAT) {
                if (k0 < 1024)
                    srcA = Ahid + ((size_t)(m & 511) * BB + (m >> 9)) * HID + k0 + seg * 8;
                else
                    srcA = Ainp + (size_t)m * 1024 + (k0 - 1024) + seg * 8;
            } else {
                srcA = Ainp + (size_t)m * 1024 + k0 + seg * 8;
            }
            cpasync16(base + row * 144 + seg * 16, srcA);
        }
        // B tile: 4 kt x 16 strips x 256B (frag-packed, contiguous per kt)
#pragma unroll
        for (int it = 0; it < 4; ++it) {
            int o = tid + it * 256;
            int ktl = o >> 8, rem = o & 255;
            const char* src = (const char*)Wp
                + ((size_t)(s * 4 + ktl) * NSTRIP + bN * 16) * 256 + rem * 16;
            cpasync16(base + 18432 + ktl * 4096 + rem * 16, src);
        }
        cp_commit();
    };

    stage(0); stage(1); stage(2);

    for (int s = 0; s < S; ++s) {
        asm volatile("cp.async.wait_group 2;" ::: "memory");
        __syncthreads();
        const uint32_t As = sb + (uint32_t)(s % 3) * FSTG;
        const char* Bs = smem + (size_t)(s % 3) * FSTG + 18432;
        const uint32_t aAddr = As + (uint32_t)(wm * 32 + (lane & 15)) * 144 + (lane >> 4) * 16;
#pragma unroll
        for (int kt = 0; kt < 4; ++kt) {
            unsigned a[2][4];
            ldsm4(a[0], aAddr + kt * 32);
            ldsm4(a[1], aAddr + 16 * 144 + kt * 32);
#pragma unroll
            for (int nt = 0; nt < 8; ++nt) {
                uint2 Bv = *(const uint2*)(Bs + (size_t)kt * 4096
                           + (wn * 8 + nt) * 256 + lane * 8);
                mma_f16(acc[0][nt], a[0], Bv.x, Bv.y);
                mma_f16(acc[1][nt], a[1], Bv.x, Bv.y);
            }
        }
        __syncthreads();
        if (s + 3 < S) stage(s + 3);
        else cp_commit();
    }

#pragma unroll
    for (int nt = 0; nt < 8; ++nt) {
        int col = bN * 128 + wn * 64 + nt * 8 + 2 * (lane & 3);
        float b0 = bias[col], b1 = bias[col + 1];
#pragma unroll
        for (int mt = 0; mt < 2; ++mt) {
            int row = bM * 128 + wm * 32 + mt * 16 + (lane >> 2);
            float v00 = acc[mt][nt][0] + b0;
            float v01 = acc[mt][nt][1] + b1;
            float v10 = acc[mt][nt][2] + b0;
            float v11 = acc[mt][nt][3] + b1;
            if (TANH) { v00 = tanhf(v00); v01 = tanhf(v01); v10 = tanhf(v10); v11 = tanhf(v11); }
            *(float2*)&C[(size_t)row * N + col]       = make_float2(v00, v01);
            *(float2*)&C[(size_t)(row + 8) * N + col] = make_float2(v10, v11);
        }
    }
}

// ----------------------------- GRU persistent kernel (R8 structure, hall store removed)
#define SM_W 0u
#define SM_A 196608u
#define PBUF 8704u
#define SM_P (196608u + 8704u)
#define SMEM_GRU 222720

__global__ void __launch_bounds__(384, 1)
gru_kernel(const float* __restrict__ Whh, const float* __restrict__ bhh,
           const int* __restrict__ x, const float* __restrict__ xproj,
           __half* __restrict__ hhi) {
    extern __shared__ char smem[];
    const uint32_t sb = smem_u32(smem);
    const int tid   = threadIdx.x;
    const int wid   = tid >> 5;
    const int lane  = tid & 31;
    const int group = blockIdx.x >> 5;        // 0..3
    const int b0    = group * 16;
    const int jc    = (blockIdx.x & 31) * 32; // 32 hidden cols
    const int gate  = wid >> 2;               // 0..2
    const int kh    = (wid >> 1) & 1;         // k-half
    const int ch    = wid & 1;                // col-half
    const int s0    = gate * 4 + ch * 2;      // W strip ids
    const int s1    = s0 + 1;

    // ---- one-time: pack W_hh slice (96 rows x 1024) into fp16 B-fragments
    for (int u = tid; u < 24576; u += 384) {
        int kt = u / 384;
        int rem = u % 384;
        int strip = rem >> 5, l = rem & 31;
        int g = strip >> 2, co = (strip & 3) * 8;
        int n = jc + co + (l >> 2);
        int k = kt * 16 + (l & 3) * 2;
        const float* wr = Whh + (size_t)(g * 1024 + n) * 1024;
        uint2 v;
        v.x = pk2h(__float2half_rn(wr[k]),     __float2half_rn(wr[k + 1]));
        v.y = pk2h(__float2half_rn(wr[k + 8]), __float2half_rn(wr[k + 9]));
        *(uint2*)(smem + SM_W + (size_t)(kt * 12 + strip) * 256 + (size_t)l * 8) = v;
    }
    __syncthreads();

    // ---- epilogue thread setup: tid<128, each owns (batch row, 4 cols)
    const int erow = tid >> 3;                // 0..15
    const int ec4  = (tid & 7) * 4;           // 0,4,..28
    const int eb   = b0 + erow;
    float hp[4] = {0.f, 0.f, 0.f, 0.f};
    float br_[4], bu_[4], bn_[4];
    if (tid < 128) {
#pragma unroll
        for (int j = 0; j < 4; ++j) {
            br_[j] = bhh[jc + ec4 + j];
            bu_[j] = bhh[1024 + jc + ec4 + j];
            bn_[j] = bhh[2048 + jc + ec4 + j];
        }
    }

    for (int t = 0; t < TT; ++t) {
        // ---- epilogue operand prefetch
        int xtok = 0;
        float4 xr, xu, xn;
        if (tid < 128) {
            xtok = x[eb * TT + t];
            const float* xb = xproj + ((size_t)eb * TT + t) * H3 + jc + ec4;
            xr = *(const float4*)xb;
            xu = *(const float4*)(xb + 1024);
            xn = *(const float4*)(xb + 2048);
        }

        if (t > 0) {
            // coarse group-flag wait: warp 0, one flag per lane
            if (wid == 0) {
                const unsigned* f = &g_flags[(group * 32 + lane) * 8];
                for (;;) {
                    unsigned v;
                    asm volatile("ld.acquire.gpu.global.u32 %0, [%1];" : "=r"(v) : "l"(f));
                    if (__all_sync(0xffffffffu, v >= (unsigned)t)) break;
                    __nanosleep(20);
                }
            }
            __syncthreads();

            // stage pair i: chunks {i, i+4} of h(t-1)
            auto stage = [&](int i) {
                if (tid < 256) {
                    int row = tid >> 4, seg = tid & 15;
                    const __half* src = hhi + ((size_t)(t - 1) * BB + b0 + row) * HID + seg * 8;
                    uint32_t dst = sb + SM_A + (uint32_t)(i % 3) * PBUF
                                 + (uint32_t)row * 272 + seg * 16;
                    cpasync16(dst,        src + i * 128);
                    cpasync16(dst + 4352, src + (i + 4) * 128);
                }
                cp_commit();
            };

            float acc[2][2][4] = {};   // [ntile][parity][4]
            stage(0); stage(1);
            for (int i = 0; i < 4; ++i) {
                if (i < 3) asm volatile("cp.async.wait_group 1;" ::: "memory");
                else       asm volatile("cp.async.wait_group 0;" ::: "memory");
                __syncthreads();
                if (i < 2) stage(i + 2);
                const uint32_t ah = sb + SM_A + (uint32_t)(i % 3) * PBUF
                                  + (uint32_t)kh * 4352
                                  + (uint32_t)(lane & 15) * 272 + (lane >> 4) * 16;
                const int ktg0 = kh * 32 + i * 8;
#pragma unroll
                for (int kt = 0; kt < 8; ++kt) {
                    unsigned aF[4];
                    ldsm4(aF, ah + kt * 32);
                    uint2 B0 = *(const uint2*)(smem + SM_W
                               + (size_t)((ktg0 + kt) * 12 + s0) * 256 + (size_t)lane * 8);
                    uint2 B1 = *(const uint2*)(smem + SM_W
                               + (size_t)((ktg0 + kt) * 12 + s1) * 256 + (size_t)lane * 8);
                    const int p = kt & 1;
                    mma_f16(acc[0][p], aF, B0.x, B0.y);
                    mma_f16(acc[1][p], aF, B1.x, B1.y);
                }
            }
            // preact partial write: [(gate*2+kh)*16 + r][36 floats]
            {
                int r  = lane >> 2;
                int cb = ch * 16 + 2 * (lane & 3);
#pragma unroll
                for (int nt = 0; nt < 2; ++nt) {
                    float d0 = acc[nt][0][0] + acc[nt][1][0];
                    float d1 = acc[nt][0][1] + acc[nt][1][1];
                    float d2 = acc[nt][0][2] + acc[nt][1][2];
                    float d3 = acc[nt][0][3] + acc[nt][1][3];
                    int col = cb + nt * 8;
                    *(float2*)(smem + SM_P
                        + (size_t)(((gate * 2 + kh) * 16 + r) * 36 + col) * 4)
                        = make_float2(d0, d1);
                    *(float2*)(smem + SM_P
                        + (size_t)(((gate * 2 + kh) * 16 + r + 8) * 36 + col) * 4)
                        = make_float2(d2, d3);
                }
            }
        }
        __syncthreads();

        // ---- epilogue: 128 threads, (row, 4 cols) each
        if (tid < 128) {
            float dr[4] = {}, du[4] = {}, dn[4] = {};
            if (t > 0) {
#pragma unroll
                for (int g = 0; g < 3; ++g) {
                    float4 a = *(const float4*)(smem + SM_P
                               + (size_t)((g * 2 + 0) * 16 + erow) * 144 + ec4 * 4);
                    float4 b = *(const float4*)(smem + SM_P
                               + (size_t)((g * 2 + 1) * 16 + erow) * 144 + ec4 * 4);
                    float* d = (g == 0) ? dr : (g == 1 ? du : dn);
                    d[0] = a.x + b.x; d[1] = a.y + b.y;
                    d[2] = a.z + b.z; d[3] = a.w + b.w;
                }
            }
            float xrv[4] = {xr.x, xr.y, xr.z, xr.w};
            float xuv[4] = {xu.x, xu.y, xu.z, xu.w};
            float xnv[4] = {xn.x, xn.y, xn.z, xn.w};
            const bool msk = (xtok == 0);   // PAD
            float hv[4];
#pragma unroll
            for (int j = 0; j < 4; ++j) {
                float rr = sigmoidf(xrv[j] + dr[j] + br_[j]);
                float uu = sigmoidf(xuv[j] + du[j] + bu_[j]);
                float nn = tanhf(xnv[j] + rr * (dn[j] + bn_[j]));
                float h  = (1.f - uu) * nn + uu * hp[j];
                hv[j] = msk ? hp[j] : h;
                hp[j] = hv[j];
            }
            uint2 uh;
            uh.x = pk2h(__float2half_rn(hv[0]), __float2half_rn(hv[1]));
            uh.y = pk2h(__float2half_rn(hv[2]), __float2half_rn(hv[3]));
            *(uint2*)(hhi + ((size_t)t * BB + eb) * HID + jc + ec4) = uh;
        }
        __syncthreads();

        // ---- release (bar gives intra-CTA HB; gpu-scope release publishes)
        if (tid == 0) {
            asm volatile("st.release.gpu.global.u32 [%0], %1;"
                         :: "l"(&g_flags[blockIdx.x * 8]), "r"((unsigned)(t + 1)) : "memory");
        }
    }
}

// ----------------------------- launch
extern "C" void kernel_launch(void* const* d_in, const int* in_sizes, int n_in,
                              void* d_out, int out_size) {
    const int*   x     = (const int*)d_in[0];
    const float* z     = (const float*)d_in[1];
    const float* emb   = (const float*)d_in[2];
    const float* W_ih  = (const float*)d_in[3];
    const float* b_ih  = (const float*)d_in[4];
    const float* W_hh  = (const float*)d_in[5];
    const float* b_hh  = (const float*)d_in[6];
    const float* W_out = (const float*)d_in[7];
    const float* b_out = (const float*)d_in[8];
    float* out = (float*)d_out;

    float *xproj_p;
    __half *inp_p, *hhi_p;
    uint2 *wihp_p, *woutp_p;
    cudaGetSymbolAddress((void**)&inp_p,   g_inp);
    cudaGetSymbolAddress((void**)&xproj_p, g_xproj);
    cudaGetSymbolAddress((void**)&hhi_p,   g_hhi);
    cudaGetSymbolAddress((void**)&wihp_p,  g_wihp);
    cudaGetSymbolAddress((void**)&woutp_p, g_woutp);

    // 1. build inp (fp16 emb||z), reset barrier flags
    build_inp_kernel<<<(unsigned)((size_t)BT * GIN / 256), 256>>>(x, z, emb);

    // 2. pack weights into fp16 fragment order
    wpack_kernel<<<3840, 256>>>(W_ih, W_out);

    // 3. x_proj = inp @ W_ih^T + b_ih   [32768 x 3072], K=1024
    {
        cudaFuncSetAttribute(gemm_f16<false, false>,
                             cudaFuncAttributeMaxDynamicSharedMemorySize, 3 * FSTG);
        dim3 grid(H3 / 128, BT / 128);
        gemm_f16<false, false><<<grid, 256, 3 * FSTG>>>(
            inp_p, nullptr, wihp_p, b_ih, xproj_p, H3, GIN);
    }

    // 4. GRU recurrence: 4 independent batch groups x 32 CTAs
    {
        cudaFuncSetAttribute(gru_kernel,
                             cudaFuncAttributeMaxDynamicSharedMemorySize, SMEM_GRU);
        gru_kernel<<<128, 384, SMEM_GRU>>>(W_hh, b_hh, x, xproj_p, hhi_p);
    }

    // 5. logits = tanh([hidden|emb] @ W_out^T + b_out)   [32768 x 512], K=1536
    {
        cudaFuncSetAttribute(gemm_f16<true, true>,
                             cudaFuncAttributeMaxDynamicSharedMemorySize, 3 * FSTG);
        dim3 grid(NIN / 128, BT / 128);
        gemm_f16<true, true><<<grid, 256, 3 * FSTG>>>(
            inp_p, hhi_p, woutp_p, b_out, out, NIN, KOUT);
    }
}